// round 6
// baseline (speedup 1.0000x reference)
#include <cuda_runtime.h>

typedef unsigned long long ull;

#define NB   128     // batch
#define NS   1000    // sequence
#define NI   64      // input dim
#define NH   512     // hidden dim

// Scratch: precomputed input projection (x @ W_ih^T + b_ih + b_hh), 262 MB.
__device__ float g_xproj[(long)NB * NS * NH];

// ---------------------------------------------------------------------------
// helpers
// ---------------------------------------------------------------------------
__device__ __forceinline__ ull fma2(ull a, ull b, ull c) {
    ull d;
    asm("fma.rn.f32x2 %0, %1, %2, %3;" : "=l"(d) : "l"(a), "l"(b), "l"(c));
    return d;
}

__device__ __forceinline__ float hadd2(ull v) {
    float lo, hi;
    asm("mov.b64 {%0, %1}, %2;" : "=f"(lo), "=f"(hi) : "l"(v));
    return lo + hi;
}

// L2-coherent (L1-bypassing) float4 load: removes any reliance on L1
// invalidation for the cross-CTA h exchange through global memory.
__device__ __forceinline__ float4 ldcg4(const float4* p) {
    float4 v;
    asm volatile("ld.global.cg.v4.f32 {%0,%1,%2,%3}, [%4];"
                 : "=f"(v.x), "=f"(v.y), "=f"(v.z), "=f"(v.w) : "l"(p));
    return v;
}

// Accurate tanh independent of -use_fast_math (series near 0 avoids the
// 1 - 2/(e^{2x}+1) cancellation; expf is accurate enough in either mode).
__device__ __forceinline__ float tanh_acc(float x) {
    float ax = fabsf(x);
    if (ax < 0.09f) {
        float x2 = x * x;
        return x + x * x2 * (-0.33333334f + 0.13333334f * x2);
    }
    float e = expf(2.0f * ax);
    float r = 1.0f - 2.0f / (e + 1.0f);
    return copysignf(r, x);
}

// ---------------------------------------------------------------------------
// Kernel A: x_proj[R][j] = sum_i x[R][i]*W_ih[j][i] + b_ih[j] + b_hh[j]
// R = b*NS + s flattened row (0..127999). Grid: 1000 CTAs x 512 thr,
// each CTA does 128 rows; thread j keeps W_ih row j (64 f32 = 32 f32x2) in regs.
// ---------------------------------------------------------------------------
__global__ __launch_bounds__(512, 1)
void xproj_kernel(const float* __restrict__ x,
                  const float* __restrict__ W_ih,
                  const float* __restrict__ b_ih,
                  const float* __restrict__ b_hh) {
    __shared__ __align__(16) float xs[16 * NI];   // 16 staged rows

    const int j = threadIdx.x;            // 0..511 = output column
    ull w[32];
    const ull* wrow = (const ull*)(W_ih + j * NI);
#pragma unroll
    for (int i = 0; i < 32; i++) w[i] = wrow[i];
    const float bias = b_ih[j] + b_hh[j];

    const long base_row = (long)blockIdx.x * 128;

    for (int rg = 0; rg < 8; rg++) {
        __syncthreads();
        // stage 16 rows (16*64 = 1024 floats, contiguous) cooperatively
        const float2* src = (const float2*)(x + (base_row + rg * 16) * NI);
        ((float2*)xs)[j] = src[j];
        __syncthreads();
#pragma unroll 1
        for (int rr = 0; rr < 16; rr++) {
            const ulonglong2* hp = (const ulonglong2*)(xs + rr * NI);
            ull acc0 = 0ULL, acc1 = 0ULL;
#pragma unroll
            for (int i = 0; i < 16; i++) {
                ulonglong2 hv = hp[i];          // broadcast LDS.128
                acc0 = fma2(w[2 * i + 0], hv.x, acc0);
                acc1 = fma2(w[2 * i + 1], hv.y, acc1);
            }
            float r = hadd2(acc0) + hadd2(acc1) + bias;
            g_xproj[(base_row + rg * 16 + rr) * NH + j] = r;
        }
    }
}

// ---------------------------------------------------------------------------
// Kernel B: recurrence. Grid = 128 CTAs, clusters of 8.
//   cluster c (0..15): batch group [8c, 8c+8)
//   rank r (0..7):     output slice j_glob in [64r, 64r+64)
// Each thread holds a 64-float slice of W_hh in registers for all 1000 steps.
// Warp mapping: warp w -> kc = w&7 (k-chunk of 64), jg = w>>3; lane l -> local
// j = jg*32+l. All lanes of a warp read the SAME h address (smem broadcast,
// conflict-free). Partial sums reduced across the 8 kc-warps through smem;
// tanh; h written to the d_out core region (a required output anyway) AND
// retained directly in h_s (own 64-col slice), so staging only re-reads the
// 7 peer slices (896 float4) through L2 (ld.global.cg) next step. One cluster
// barrier (arrive=release / wait=acquire at cluster scope) per step orders
// the global h writes against the peers' next-step reads. The x_proj
// prefetch for step t+1 is issued BETWEEN arrive and wait so its DRAM
// latency rides out the barrier instead of the post-wait critical path.
//
// Ordering of the own-slice smem retention: the reduce-phase h_s write is
// separated from this step's dot-phase reads by the preceding __syncthreads,
// and from the NEXT step's dot-phase reads by the staging __syncthreads.
// ---------------------------------------------------------------------------
__global__ __launch_bounds__(512, 1) __cluster_dims__(8, 1, 1)
void rnn_kernel(const float* __restrict__ W_hh, float* core /* = d_out */) {
    __shared__ __align__(16) float h_s[8 * NH];   // [b_local][k]   16 KB
    __shared__ float red[8 * NH];                 // [b_local][kc*64+j] 16 KB

    const int tid  = threadIdx.x;
    const int w    = tid >> 5;
    const int l    = tid & 31;
    const int kc   = w & 7;                 // k-chunk (64 wide)
    const int jg   = w >> 3;                // 0..1
    const int j    = jg * 32 + l;           // local output 0..63

    const int cid  = blockIdx.x >> 3;       // cluster id 0..15
    const int rank = blockIdx.x & 7;        // slice rank 0..7
    const int bg   = cid * 8;               // first global batch
    const int jglob = rank * 64 + j;

    // reduce-phase identity: thread u -> (batch rb, local col rj)
    const int rb = tid >> 6;                // 0..7
    const int rj = tid & 63;                // 0..63
    const int rjglob = rank * 64 + rj;

    // this thread's x_proj / output column stream: stride NH per step
    const float* xp_ptr  = &g_xproj[((long)(bg + rb) * NS) * NH + rjglob];
    float*       out_ptr = &core    [((long)(bg + rb) * NS) * NH + rjglob];

    // own slice in f4-col units: [own_q0, own_q0+16) is retained, not staged
    const int own_q0 = rank * 16;

    // W_hh[jglob][kc*64 .. kc*64+64) in registers (as 32 f32x2)
    ull wr[32];
    const ull* wsrc = (const ull*)(W_hh + (long)jglob * NH + kc * 64);
#pragma unroll
    for (int i = 0; i < 32; i++) wr[i] = wsrc[i];

    // staging identity (computed once): two flat passes over 896 peer float4s
    // (8 batches x 112 peer f4-cols); pass p covers idx = tid + 512*p.
    const int sb0 = tid / 112;                       // pass-0 batch
    const int sq0t = tid - sb0 * 112;                //        peer col
    const int sq0 = sq0t + (sq0t >= own_q0 ? 16 : 0);
    const int idx1 = tid + 512;
    const int sb1 = idx1 / 112;                      // pass-1 batch
    const int sq1t = idx1 - sb1 * 112;               //        peer col
    const int sq1 = sq1t + (sq1t >= own_q0 ? 16 : 0);
    const bool p1 = (tid < 384);

    // ---- peeled step t = 0: h_prev = 0, so h_new = tanh(x_proj) ----
    float xp;   // x_proj value for the NEXT step, prefetched across barriers
    {
        float hn0 = tanh_acc(__ldg(xp_ptr));
        out_ptr[0] = hn0;
        h_s[rb * NH + rjglob] = hn0;      // retain own slice for t=1
        asm volatile("barrier.cluster.arrive.aligned;" ::: "memory");
        xp = __ldg(xp_ptr + NH);          // prefetch t=1 under the barrier
        asm volatile("barrier.cluster.wait.aligned;"   ::: "memory");
    }

    // ---- steady state t = 1 .. NS-1 ----
    for (int t = 1; t < NS; t++) {
        // stage the 7 PEER slices of h_prev (896 float4) into smem,
        // L1-bypassing; own slice is already resident from last step.
        {
            const float4* s0 =
                (const float4*)(core + ((long)(bg + sb0) * NS + (t - 1)) * NH) + sq0;
            ((float4*)h_s)[sb0 * 128 + sq0] = ldcg4(s0);
            if (p1) {
                const float4* s1 =
                    (const float4*)(core + ((long)(bg + sb1) * NS + (t - 1)) * NH) + sq1;
                ((float4*)h_s)[sb1 * 128 + sq1] = ldcg4(s1);
            }
        }
        __syncthreads();

        // partial dot products: per batch, 64-long chunk against register W.
        // unroll 2 bounds the live range (64 W-regs resident; no spills).
#pragma unroll 2
        for (int b = 0; b < 8; b++) {
            const ulonglong2* hp = (const ulonglong2*)(h_s + b * NH + kc * 64);
            ull acc0 = 0ULL, acc1 = 0ULL;
#pragma unroll
            for (int i = 0; i < 16; i++) {
                ulonglong2 hv = hp[i];            // broadcast LDS.128
                acc0 = fma2(wr[2 * i + 0], hv.x, acc0);
                acc1 = fma2(wr[2 * i + 1], hv.y, acc1);
            }
            red[b * NH + kc * 64 + j] = hadd2(acc0) + hadd2(acc1);
        }
        __syncthreads();   // orders h_s dot-reads above vs. own-slice write below

        // reduce over the 8 k-chunks, tanh, write h_new (coalesced 256B/group)
        float s = xp;
#pragma unroll
        for (int c = 0; c < 8; c++) s += red[rb * NH + c * 64 + rj];
        float hn = tanh_acc(s);
        out_ptr[(long)t * NH] = hn;          // global: for peers + final output
        h_s[rb * NH + rjglob] = hn;          // smem:   retain own slice locally

        // release this step's h, prefetch next xp under the barrier, acquire
        asm volatile("barrier.cluster.arrive.aligned;" ::: "memory");
        if (t + 1 < NS) xp = __ldg(xp_ptr + (long)(t + 1) * NH);
        asm volatile("barrier.cluster.wait.aligned;"   ::: "memory");
    }
}

// ---------------------------------------------------------------------------
// Kernel C: readout. One warp per (b,t) row: two 512-dots, warp-reduced.
// ---------------------------------------------------------------------------
__global__ __launch_bounds__(512)
void readout_kernel(const float* __restrict__ core,
                    const float* __restrict__ W_ro,
                    const float* __restrict__ b_ro,
                    const float* __restrict__ W_sig,
                    const float* __restrict__ b_sig,
                    float* __restrict__ out_ro,
                    float* __restrict__ out_sig) {
    const int warp = threadIdx.x >> 5;
    const int lane = threadIdx.x & 31;
    const long row = (long)blockIdx.x * 16 + warp;   // 0..127999

    // lane-private weight chunks (16 floats each), register resident
    float4 wro[4], wsg[4];
    const float4* wr4 = (const float4*)W_ro  + lane * 4;
    const float4* ws4 = (const float4*)W_sig + lane * 4;
#pragma unroll
    for (int i = 0; i < 4; i++) { wro[i] = wr4[i]; wsg[i] = ws4[i]; }

    const float4* c4 = (const float4*)(core + row * NH) + lane * 4;
    float dro = 0.f, dsg = 0.f;
#pragma unroll
    for (int i = 0; i < 4; i++) {
        float4 h = c4[i];
        dro += h.x * wro[i].x + h.y * wro[i].y + h.z * wro[i].z + h.w * wro[i].w;
        dsg += h.x * wsg[i].x + h.y * wsg[i].y + h.z * wsg[i].z + h.w * wsg[i].w;
    }
#pragma unroll
    for (int off = 16; off > 0; off >>= 1) {
        dro += __shfl_down_sync(0xFFFFFFFFu, dro, off);
        dsg += __shfl_down_sync(0xFFFFFFFFu, dsg, off);
    }
    if (lane == 0) {
        out_ro[row] = dro + b_ro[0];
        float z = dsg + b_sig[0];
        out_sig[row] = 1.0f / (1.0f + expf(-z));
    }
}

// ---------------------------------------------------------------------------
// launch
// ---------------------------------------------------------------------------
extern "C" void kernel_launch(void* const* d_in, const int* in_sizes, int n_in,
                              void* d_out, int out_size) {
    const float* x     = (const float*)d_in[0];
    const float* W_ih  = (const float*)d_in[1];
    const float* W_hh  = (const float*)d_in[2];
    const float* b_ih  = (const float*)d_in[3];
    const float* b_hh  = (const float*)d_in[4];
    const float* W_ro  = (const float*)d_in[5];
    const float* b_ro  = (const float*)d_in[6];
    const float* W_sig = (const float*)d_in[7];
    const float* b_sig = (const float*)d_in[8];

    float* out  = (float*)d_out;
    float* core = out;                                   // (B,S,H)
    float* oro  = out + (long)NB * NS * NH;              // (B,S,1)
    float* osig = oro + (long)NB * NS;                   // (B,S,1)

    // 1) input projection (+ both biases folded)
    xproj_kernel<<<1000, 512>>>(x, W_ih, b_ih, b_hh);

    // 2) recurrence: 16 clusters x 8 CTAs, one resident wave
    rnn_kernel<<<128, 512>>>(W_hh, core);

    // 3) readouts: one warp per (b,t) row
    readout_kernel<<<8000, 512>>>(core, W_ro, b_ro, W_sig, b_sig, oro, osig);
}

// round 15
// speedup vs baseline: 1.2169x; 1.2169x over previous
#include <cuda_runtime.h>

typedef unsigned long long ull;

#define NB   128     // batch
#define NS   1000    // sequence
#define NI   64      // input dim
#define NH   512     // hidden dim

// Scratch: precomputed input projection (x @ W_ih^T + b_ih + b_hh), 262 MB.
__device__ float g_xproj[(long)NB * NS * NH];

// ---------------------------------------------------------------------------
// helpers
// ---------------------------------------------------------------------------
__device__ __forceinline__ ull fma2(ull a, ull b, ull c) {
    ull d;
    asm("fma.rn.f32x2 %0, %1, %2, %3;" : "=l"(d) : "l"(a), "l"(b), "l"(c));
    return d;
}

__device__ __forceinline__ float hadd2(ull v) {
    float lo, hi;
    asm("mov.b64 {%0, %1}, %2;" : "=f"(lo), "=f"(hi) : "l"(v));
    return lo + hi;
}

// L2-coherent (L1-bypassing) float4 load for the cross-CTA h exchange.
__device__ __forceinline__ float4 ldcg4(const float4* p) {
    float4 v;
    asm volatile("ld.global.cg.v4.f32 {%0,%1,%2,%3}, [%4];"
                 : "=f"(v.x), "=f"(v.y), "=f"(v.z), "=f"(v.w) : "l"(p));
    return v;
}

// Accurate tanh independent of -use_fast_math.
__device__ __forceinline__ float tanh_acc(float x) {
    float ax = fabsf(x);
    if (ax < 0.09f) {
        float x2 = x * x;
        return x + x * x2 * (-0.33333334f + 0.13333334f * x2);
    }
    float e = expf(2.0f * ax);
    float r = 1.0f - 2.0f / (e + 1.0f);
    return copysignf(r, x);
}

// ---------------------------------------------------------------------------
// Kernel A: x_proj (343us measured, 4% of runtime — untouched)
// ---------------------------------------------------------------------------
__global__ __launch_bounds__(512, 1)
void xproj_kernel(const float* __restrict__ x,
                  const float* __restrict__ W_ih,
                  const float* __restrict__ b_ih,
                  const float* __restrict__ b_hh) {
    __shared__ __align__(16) float xs[16 * NI];   // 16 staged rows

    const int j = threadIdx.x;            // 0..511 = output column
    ull w[32];
    const ull* wrow = (const ull*)(W_ih + j * NI);
#pragma unroll
    for (int i = 0; i < 32; i++) w[i] = wrow[i];
    const float bias = b_ih[j] + b_hh[j];

    const long base_row = (long)blockIdx.x * 128;

    for (int rg = 0; rg < 8; rg++) {
        __syncthreads();
        const float2* src = (const float2*)(x + (base_row + rg * 16) * NI);
        ((float2*)xs)[j] = src[j];
        __syncthreads();
#pragma unroll 1
        for (int rr = 0; rr < 16; rr++) {
            const ulonglong2* hp = (const ulonglong2*)(xs + rr * NI);
            ull acc0 = 0ULL, acc1 = 0ULL;
#pragma unroll
            for (int i = 0; i < 16; i++) {
                ulonglong2 hv = hp[i];          // broadcast LDS.128
                acc0 = fma2(w[2 * i + 0], hv.x, acc0);
                acc1 = fma2(w[2 * i + 1], hv.y, acc1);
            }
            float r = hadd2(acc0) + hadd2(acc1) + bias;
            g_xproj[(base_row + rg * 16 + rr) * NH + j] = r;
        }
    }
}

// ---------------------------------------------------------------------------
// Kernel B: recurrence. Grid = 128 CTAs, clusters of 8, 256 THREADS/CTA.
//   cluster c (0..15): batch group [8c, 8c+8)
//   rank r (0..7):     output slice j_glob in [64r, 64r+64)
// 256 threads -> reg cap 256/thread (R6's 512thr/128-reg cap is the spill
// suspect for the 14k cyc/step observed). Warp w = kc (k-chunk of 64);
// lane l computes TWO output columns j0=l, j1=l+32, sharing every h operand
// (halves LDS, 4 independent FMA chains/thread). W slice: 128 regs/thread,
// resident all 1000 steps. Partials reduced across the 8 kc-warps via smem;
// tanh; h written to the d_out core region AND retained in h_s (own 64-col
// slice); staging re-reads only the 7 peer slices (896 float4) via
// ld.global.cg. One cluster barrier per step; x_proj prefetch for t+1 is
// issued between arrive and wait (guarded at the tail — no OOB read).
// All per-step global pointers are incremented (+NH), not recomputed.
// ---------------------------------------------------------------------------
__global__ __launch_bounds__(256, 1) __cluster_dims__(8, 1, 1)
void rnn_kernel(const float* __restrict__ W_hh, float* core /* = d_out */) {
    __shared__ __align__(16) float h_s[8 * NH];   // [b_local][k]   16 KB
    __shared__ float red[8 * NH];                 // [b_local][kc*64+j] 16 KB

    const int tid  = threadIdx.x;           // 0..255
    const int kc   = tid >> 5;              // warp = k-chunk (64 wide), 0..7
    const int l    = tid & 31;
    const int j0   = l;                     // local output cols
    const int j1   = l + 32;

    const int cid  = blockIdx.x >> 3;       // cluster id 0..15
    const int rank = blockIdx.x & 7;        // slice rank 0..7
    const int bg   = cid * 8;               // first global batch

    // reduce/output identity: two items per thread: tid and tid+256
    const int rbA = tid >> 6;               // 0..3
    const int rbB = rbA + 4;                // 4..7
    const int rj  = tid & 63;
    const int rjglob = rank * 64 + rj;

    // per-item x_proj / output streams, incremented by NH per step
    const float* xpA_ptr = &g_xproj[((long)(bg + rbA) * NS) * NH + rjglob];
    const float* xpB_ptr = &g_xproj[((long)(bg + rbB) * NS) * NH + rjglob];
    float*       outA    = &core    [((long)(bg + rbA) * NS) * NH + rjglob];
    float*       outB    = &core    [((long)(bg + rbB) * NS) * NH + rjglob];

    // own slice in f4-col units: [own_q0, own_q0+16) retained, not staged
    const int own_q0 = rank * 16;

    // W_hh rows for j0 and j1 over this warp's k-chunk: 2x32 ull = 128 regs
    ull wr0[32], wr1[32];
    {
        const ull* w0 = (const ull*)(W_hh + (long)(rank * 64 + j0) * NH + kc * 64);
        const ull* w1 = (const ull*)(W_hh + (long)(rank * 64 + j1) * NH + kc * 64);
#pragma unroll
        for (int i = 0; i < 32; i++) { wr0[i] = w0[i]; wr1[i] = w1[i]; }
    }

    // staging identity: 896 peer float4s (8 batches x 112 peer f4-cols),
    // four flat passes: idx = tid + 256*p (p=3 only for tid<128).
    // Source pointers hoisted: walk +NH floats (= +128 float4) per step.
    const float4* sp[4];
    int sdst[4];
#pragma unroll
    for (int p = 0; p < 4; p++) {
        int idx = tid + 256 * p;
        int b   = idx / 112;
        int qt  = idx - b * 112;
        int q   = qt + (qt >= own_q0 ? 16 : 0);
        sdst[p] = b * 128 + q;
        sp[p]   = (const float4*)(core + (long)(bg + b) * NS * NH) + q;
    }
    const bool p3 = (tid < 128);

    // ---- peeled step t = 0: h_prev = 0, so h_new = tanh(x_proj) ----
    float xpA, xpB;   // x_proj for the NEXT step, prefetched across barriers
    {
        float hA = tanh_acc(__ldg(xpA_ptr));
        float hB = tanh_acc(__ldg(xpB_ptr));
        outA[0] = hA;  h_s[rbA * NH + rjglob] = hA;
        outB[0] = hB;  h_s[rbB * NH + rjglob] = hB;
        asm volatile("barrier.cluster.arrive.aligned;" ::: "memory");
        xpA = __ldg(xpA_ptr + NH);
        xpB = __ldg(xpB_ptr + NH);
        xpA_ptr += 2 * NH;   // now points at t=2
        xpB_ptr += 2 * NH;
        outA += NH;          // now points at t=1
        outB += NH;
        asm volatile("barrier.cluster.wait.aligned;"   ::: "memory");
    }

    // ---- steady state t = 1 .. NS-1 ----
    for (int t = 1; t < NS; t++) {
        // stage the 7 PEER slices of h_prev (896 float4), L1-bypassing;
        // own slice already resident from last step's reduce.
        ((float4*)h_s)[sdst[0]] = ldcg4(sp[0]);
        ((float4*)h_s)[sdst[1]] = ldcg4(sp[1]);
        ((float4*)h_s)[sdst[2]] = ldcg4(sp[2]);
        if (p3) ((float4*)h_s)[sdst[3]] = ldcg4(sp[3]);
#pragma unroll
        for (int p = 0; p < 4; p++) sp[p] += NH / 4;   // advance one step
        __syncthreads();

        // partial dot products: per batch, this warp's 64-chunk x 2 columns.
        // h operands shared between the two columns (4 indep FMA chains).
#pragma unroll 1
        for (int b = 0; b < 8; b++) {
            const ulonglong2* hp = (const ulonglong2*)(h_s + b * NH + kc * 64);
            ull a00 = 0ULL, a01 = 0ULL, a10 = 0ULL, a11 = 0ULL;
#pragma unroll
            for (int i = 0; i < 16; i++) {
                ulonglong2 hv = hp[i];            // broadcast LDS.128
                a00 = fma2(wr0[2 * i + 0], hv.x, a00);
                a01 = fma2(wr0[2 * i + 1], hv.y, a01);
                a10 = fma2(wr1[2 * i + 0], hv.x, a10);
                a11 = fma2(wr1[2 * i + 1], hv.y, a11);
            }
            red[b * NH + kc * 64 + j0] = hadd2(a00) + hadd2(a01);
            red[b * NH + kc * 64 + j1] = hadd2(a10) + hadd2(a11);
        }
        __syncthreads();   // orders dot-phase h_s reads vs. retention writes

        // reduce over the 8 k-chunks, tanh, write h_new (both items)
        float sA = xpA, sB = xpB;
#pragma unroll
        for (int c = 0; c < 8; c++) {
            sA += red[rbA * NH + c * 64 + rj];
            sB += red[rbB * NH + c * 64 + rj];
        }
        float hA = tanh_acc(sA);
        float hB = tanh_acc(sB);
        *outA = hA;  h_s[rbA * NH + rjglob] = hA;  outA += NH;
        *outB = hB;  h_s[rbB * NH + rjglob] = hB;  outB += NH;

        // release this step's h, prefetch next xp under the barrier
        // (guarded: at t = NS-1 the next step doesn't exist and the
        // unguarded load would read past the end of g_xproj), acquire.
        asm volatile("barrier.cluster.arrive.aligned;" ::: "memory");
        if (t + 1 < NS) {
            xpA = __ldg(xpA_ptr);  xpA_ptr += NH;
            xpB = __ldg(xpB_ptr);  xpB_ptr += NH;
        }
        asm volatile("barrier.cluster.wait.aligned;"   ::: "memory");
    }
}

// ---------------------------------------------------------------------------
// Kernel C: readout. One warp per (b,t) row: two 512-dots, warp-reduced.
// ---------------------------------------------------------------------------
__global__ __launch_bounds__(512)
void readout_kernel(const float* __restrict__ core,
                    const float* __restrict__ W_ro,
                    const float* __restrict__ b_ro,
                    const float* __restrict__ W_sig,
                    const float* __restrict__ b_sig,
                    float* __restrict__ out_ro,
                    float* __restrict__ out_sig) {
    const int warp = threadIdx.x >> 5;
    const int lane = threadIdx.x & 31;
    const long row = (long)blockIdx.x * 16 + warp;   // 0..127999

    float4 wro[4], wsg[4];
    const float4* wr4 = (const float4*)W_ro  + lane * 4;
    const float4* ws4 = (const float4*)W_sig + lane * 4;
#pragma unroll
    for (int i = 0; i < 4; i++) { wro[i] = wr4[i]; wsg[i] = ws4[i]; }

    const float4* c4 = (const float4*)(core + row * NH) + lane * 4;
    float dro = 0.f, dsg = 0.f;
#pragma unroll
    for (int i = 0; i < 4; i++) {
        float4 h = c4[i];
        dro += h.x * wro[i].x + h.y * wro[i].y + h.z * wro[i].z + h.w * wro[i].w;
        dsg += h.x * wsg[i].x + h.y * wsg[i].y + h.z * wsg[i].z + h.w * wsg[i].w;
    }
#pragma unroll
    for (int off = 16; off > 0; off >>= 1) {
        dro += __shfl_down_sync(0xFFFFFFFFu, dro, off);
        dsg += __shfl_down_sync(0xFFFFFFFFu, dsg, off);
    }
    if (lane == 0) {
        out_ro[row] = dro + b_ro[0];
        float z = dsg + b_sig[0];
        out_sig[row] = 1.0f / (1.0f + expf(-z));
    }
}

// ---------------------------------------------------------------------------
// launch
// ---------------------------------------------------------------------------
extern "C" void kernel_launch(void* const* d_in, const int* in_sizes, int n_in,
                              void* d_out, int out_size) {
    const float* x     = (const float*)d_in[0];
    const float* W_ih  = (const float*)d_in[1];
    const float* W_hh  = (const float*)d_in[2];
    const float* b_ih  = (const float*)d_in[3];
    const float* b_hh  = (const float*)d_in[4];
    const float* W_ro  = (const float*)d_in[5];
    const float* b_ro  = (const float*)d_in[6];
    const float* W_sig = (const float*)d_in[7];
    const float* b_sig = (const float*)d_in[8];

    float* out  = (float*)d_out;
    float* core = out;                                   // (B,S,H)
    float* oro  = out + (long)NB * NS * NH;              // (B,S,1)
    float* osig = oro + (long)NB * NS;                   // (B,S,1)

    // 1) input projection (+ both biases folded)
    xproj_kernel<<<1000, 512>>>(x, W_ih, b_ih, b_hh);

    // 2) recurrence: 16 clusters x 8 CTAs, 256 threads, one resident wave
    rnn_kernel<<<128, 256>>>(W_hh, core);

    // 3) readouts: one warp per (b,t) row
    readout_kernel<<<8000, 512>>>(core, W_ro, b_ro, W_sig, b_sig, oro, osig);
}